// round 16
// baseline (speedup 1.0000x reference)
#include <cuda_runtime.h>
#include <math_constants.h>

#define N_NODES 50000
#define N_EDGES 1200000
#define N_GRAPHS 512
#define D1 64
#define NF 92
#define NG 50
#define BN_EPS 1e-5f
#define LOG2F_C 0.6931471805599453f

#define N_TILES (N_EDGES / 128)   // 9375
#define EDGE_GRID 444             // 3 CTAs/SM * 148

typedef unsigned long long ull;

// -------------------- device scratch --------------------
__device__ float g_out[N_NODES * D1];
__device__ float g_h[N_NODES * D1];
__device__ float g_agg[N_NODES * D1];
__device__ float g_bnstats[2 * D1];
__device__ float g_pool[N_GRAPHS * D1];
__device__ float g_cnt[N_GRAPHS];
__device__ int   g_hist[N_NODES];
__device__ int4  g_meta[N_EDGES];   // {src, dst, C-bits, orig edge id}, dst-sorted

// -------------------- helpers --------------------
__device__ __forceinline__ ull ffma2(ull a, ull b, ull c) {
    ull d;
    asm("fma.rn.f32x2 %0, %1, %2, %3;" : "=l"(d) : "l"(a), "l"(b), "l"(c));
    return d;
}
__device__ __forceinline__ ull dup2(float v) {
    ull r;
    asm("mov.b64 %0, {%1, %1};" : "=l"(r) : "f"(v));
    return r;
}
__device__ __forceinline__ float f2lo(ull v) { return __uint_as_float((unsigned)(v & 0xffffffffull)); }
__device__ __forceinline__ float f2hi(ull v) { return __uint_as_float((unsigned)(v >> 32)); }

__device__ __forceinline__ float sspf(float v) {
    return fmaxf(v, 0.f) + __logf(1.f + __expf(-fabsf(v))) - LOG2F_C;
}

__device__ __forceinline__ void red4(float* p, float4 v) {
    asm volatile("red.global.add.v4.f32 [%0], {%1,%2,%3,%4};"
                 :: "l"(p), "f"(v.x), "f"(v.y), "f"(v.z), "f"(v.w) : "memory");
}

__device__ __forceinline__ void cp8(unsigned dst, const void* src) {
    asm volatile("cp.async.ca.shared.global [%0], [%1], 8;" :: "r"(dst), "l"(src));
}
__device__ __forceinline__ void cp_commit() {
    asm volatile("cp.async.commit_group;" ::: "memory");
}
__device__ __forceinline__ void cp_wait0() {
    asm volatile("cp.async.wait_group 0;" ::: "memory");
}
__device__ __forceinline__ void prefetchL2(const void* p) {
    asm volatile("prefetch.global.L2 [%0];" :: "l"(p));
}
// pack two f32 -> f16x2 (lo = first arg)
__device__ __forceinline__ unsigned h2pk(float lo, float hi) {
    unsigned d;
    asm("cvt.rn.f16x2.f32 %0, %1, %2;" : "=r"(d) : "f"(hi), "f"(lo));
    return d;
}
__device__ __forceinline__ void mma_f16(float& c0, float& c1, float& c2, float& c3,
                                        unsigned a0, unsigned a1, unsigned a2, unsigned a3,
                                        unsigned b0, unsigned b1) {
    asm volatile("mma.sync.aligned.m16n8k16.row.col.f32.f16.f16.f32 "
                 "{%0,%1,%2,%3}, {%4,%5,%6,%7}, {%8,%9}, {%0,%1,%2,%3};"
                 : "+f"(c0), "+f"(c1), "+f"(c2), "+f"(c3)
                 : "r"(a0), "r"(a1), "r"(a2), "r"(a3), "r"(b0), "r"(b1));
}

// =====================================================================
// counting sort by dst; scatter materializes packed sorted meta
// =====================================================================
__global__ void k_hist(const int* __restrict__ ei) {
    int i = blockIdx.x * blockDim.x + threadIdx.x;
    if (i < N_EDGES) atomicAdd(&g_hist[ei[N_EDGES + i]], 1);
}

__global__ __launch_bounds__(1024) void k_scan() {
    __shared__ int ss[1024];
    int t = threadIdx.x;
    int lo = t * 49;
    int hi = min(lo + 49, N_NODES);
    int s = 0;
    for (int b = lo; b < hi; b++) s += g_hist[b];
    ss[t] = s;
    __syncthreads();
    for (int off = 1; off < 1024; off <<= 1) {
        int v = (t >= off) ? ss[t - off] : 0;
        __syncthreads();
        ss[t] += v;
        __syncthreads();
    }
    int run = ss[t] - s;
    for (int b = lo; b < hi; b++) {
        int c = g_hist[b];
        g_hist[b] = run;
        run += c;
    }
}

__global__ void k_scatter(const int* __restrict__ ei, const float* __restrict__ ew) {
    int i = blockIdx.x * blockDim.x + threadIdx.x;
    if (i < N_EDGES) {
        int dst = ei[N_EDGES + i];
        int pos = atomicAdd(&g_hist[dst], 1);
        int4 m;
        m.x = ei[i];
        m.y = dst;
        m.z = __float_as_int(0.5f * (cospif(ew[i] * 0.125f) + 1.f));
        m.w = i;
        g_meta[pos] = m;
    }
}

// =====================================================================
// pre FC (block-tile f32x2 GEMM, 128-node tiles) — unchanged
// =====================================================================
#define PRE_SMEM ((5888 + 12032 + 64) * 4)
__global__ __launch_bounds__(256, 2) void k_pre(const float* __restrict__ x,
                                                const float* __restrict__ W,
                                                const float* __restrict__ b) {
    extern __shared__ float sm[];
    float* sWt = sm;            // [92][64] k-major
    float* sA = sm + 5888;      // [128][94]
    float* sB = sm + 17920;     // [64]

    int tid = threadIdx.x;
    int tx = tid & 7, ty = tid >> 3;
    int n0 = blockIdx.x * 128;

    for (int i = tid; i < 92 * 64; i += 256) {
        int f = i / 92, k = i - f * 92;
        sWt[k * 64 + f] = W[i];
    }
    if (tid < 64) sB[tid] = b[tid];
    for (int i = tid; i < 128 * 92; i += 256) {
        int r = i / 92, k = i - r * 92;
        int n = n0 + r;
        sA[r * 94 + k] = (n < N_NODES) ? x[(size_t)n * NF + k] : 0.f;
    }
    __syncthreads();

    ull acc[4][4];
#pragma unroll
    for (int j = 0; j < 4; j++)
#pragma unroll
        for (int p = 0; p < 4; p++) acc[j][p] = 0ull;

#pragma unroll 4
    for (int k = 0; k < 92; k++) {
        ulonglong2 bA = *(const ulonglong2*)&sWt[k * 64 + 8 * tx];
        ulonglong2 bB = *(const ulonglong2*)&sWt[k * 64 + 8 * tx + 4];
#pragma unroll
        for (int j = 0; j < 4; j++) {
            ull av = dup2(sA[(4 * ty + j) * 94 + k]);
            acc[j][0] = ffma2(av, bA.x, acc[j][0]);
            acc[j][1] = ffma2(av, bA.y, acc[j][1]);
            acc[j][2] = ffma2(av, bB.x, acc[j][2]);
            acc[j][3] = ffma2(av, bB.y, acc[j][3]);
        }
    }

#pragma unroll
    for (int j = 0; j < 4; j++) {
        int n = n0 + 4 * ty + j;
        if (n < N_NODES) {
            float4 o0, o1;
            o0.x = fmaxf(f2lo(acc[j][0]) + sB[8 * tx + 0], 0.f);
            o0.y = fmaxf(f2hi(acc[j][0]) + sB[8 * tx + 1], 0.f);
            o0.z = fmaxf(f2lo(acc[j][1]) + sB[8 * tx + 2], 0.f);
            o0.w = fmaxf(f2hi(acc[j][1]) + sB[8 * tx + 3], 0.f);
            o1.x = fmaxf(f2lo(acc[j][2]) + sB[8 * tx + 4], 0.f);
            o1.y = fmaxf(f2hi(acc[j][2]) + sB[8 * tx + 5], 0.f);
            o1.z = fmaxf(f2lo(acc[j][3]) + sB[8 * tx + 6], 0.f);
            o1.w = fmaxf(f2hi(acc[j][3]) + sB[8 * tx + 7], 0.f);
            *(float4*)&g_out[(size_t)n * D1 + 8 * tx] = o0;
            *(float4*)&g_out[(size_t)n * D1 + 8 * tx + 4] = o1;
        }
    }
}

// =====================================================================
// lin1 v2: fp32 warp-tile, non-duplicated A (dup2 in regs), warp-private
// row staging with fused BN, 50.7KB smem -> 3 CTAs/SM.
//   tx=tid&7: feats 8tx..8tx+7; ty=tid>>3: rows 4ty..4ty+3 (warp-local)
// =====================================================================
#define LIN1_SMEM ((4096 + 8448 + 128) * 4)
__global__ __launch_bounds__(256, 3) void k_lin1(const float* __restrict__ W,
                                                 const float* __restrict__ bng,
                                                 const float* __restrict__ bnb,
                                                 int apply_bn) {
    extern __shared__ float sm[];
    float* sWt = sm;           // [64][64] k-major
    float* sA  = sm + 4096;    // [128][66]
    float* sSc = sm + 12544;
    float* sOf = sSc + 64;

    int tid = threadIdx.x;
    int tx = tid & 7, ty = tid >> 3;
    int lane = tid & 31, w = tid >> 5;
    int R0 = 16 * w;
    int n0 = blockIdx.x * 128;

    for (int i = tid; i < 64 * 64; i += 256) {
        int f = i >> 6, k = i & 63;
        sWt[k * 64 + f] = W[i];
    }
    if (tid < 64) {
        if (apply_bn) {
            const float invN = 1.f / (float)N_NODES;
            float mu = g_bnstats[tid] * invN;
            float var = fmaxf(g_bnstats[64 + tid] * invN - mu * mu, 0.f);
            float sc = rsqrtf(var + BN_EPS) * bng[tid];
            sSc[tid] = sc;
            sOf[tid] = bnb[tid] - mu * sc;
        } else {
            sSc[tid] = 1.f;
            sOf[tid] = 0.f;
        }
    }
    __syncthreads();

    // ---- warp-private row staging (BN applied + written back) ----
    {
        int r = lane >> 1, half = lane & 1;
        int n = n0 + R0 + r;
        float* dst = &sA[(R0 + r) * 66 + 32 * half];
        if (n < N_NODES) {
            float* srcp = &g_out[(size_t)n * D1 + 32 * half];
            if (apply_bn) {
#pragma unroll
                for (int q = 0; q < 16; q++) {
                    float2 v = *(const float2*)&srcp[2 * q];
                    int cb = 32 * half + 2 * q;
                    v.x = v.x * sSc[cb] + sOf[cb];
                    v.y = v.y * sSc[cb + 1] + sOf[cb + 1];
                    *(float2*)&srcp[2 * q] = v;      // write normalized back
                    *(float2*)&dst[2 * q] = v;
                }
            } else {
#pragma unroll
                for (int q = 0; q < 16; q++)
                    *(float2*)&dst[2 * q] = *(const float2*)&srcp[2 * q];
            }
        } else {
#pragma unroll
            for (int q = 0; q < 16; q++)
                *(float2*)&dst[2 * q] = make_float2(0.f, 0.f);
        }
    }
    __syncwarp();

    // ---- GEMM: g_h = out_norm @ W.T, K=64 ----
    ull acc[4][4];
#pragma unroll
    for (int j = 0; j < 4; j++)
#pragma unroll
        for (int p = 0; p < 4; p++) acc[j][p] = 0ull;

#pragma unroll 8
    for (int k = 0; k < 64; k++) {
        ulonglong2 bA = *(const ulonglong2*)&sWt[k * 64 + 8 * tx];
        ulonglong2 bB = *(const ulonglong2*)&sWt[k * 64 + 8 * tx + 4];
#pragma unroll
        for (int j = 0; j < 4; j++) {
            ull av = dup2(sA[(4 * ty + j) * 66 + k]);
            acc[j][0] = ffma2(av, bA.x, acc[j][0]);
            acc[j][1] = ffma2(av, bA.y, acc[j][1]);
            acc[j][2] = ffma2(av, bB.x, acc[j][2]);
            acc[j][3] = ffma2(av, bB.y, acc[j][3]);
        }
    }

#pragma unroll
    for (int j = 0; j < 4; j++) {
        int n = n0 + 4 * ty + j;
        if (n < N_NODES) {
            float4 o0, o1;
            o0.x = f2lo(acc[j][0]); o0.y = f2hi(acc[j][0]);
            o0.z = f2lo(acc[j][1]); o0.w = f2hi(acc[j][1]);
            o1.x = f2lo(acc[j][2]); o1.y = f2hi(acc[j][2]);
            o1.z = f2lo(acc[j][3]); o1.w = f2hi(acc[j][3]);
            *(float4*)&g_h[(size_t)n * D1 + 8 * tx] = o0;
            *(float4*)&g_h[(size_t)n * D1 + 8 * tx + 4] = o1;
        }
    }
}

// =====================================================================
// k_edge v13: R15 + next-tile eperm hoist + L2 prefetch at tile top
// (late cp.async fill then hits L2 ~234cyc instead of DRAM ~600cyc)
// =====================================================================
#define EDGE_SW1   0                  // uint [16][136] = 2176
#define EDGE_SW2   2176               // uint [16][136] = 2176
#define EDGE_BUF   4352               // float [128][72] = 9216
#define EDGE_B1    13568
#define EDGE_B2    13632
#define EDGE_SMEM_WORDS 13696
#define EDGE_SMEM (EDGE_SMEM_WORDS * 4)

__global__ __launch_bounds__(256, 3) void k_edge(const float* __restrict__ EA,
                                                 const float* __restrict__ W1,
                                                 const float* __restrict__ bias1,
                                                 const float* __restrict__ W2,
                                                 const float* __restrict__ bias2) {
    extern __shared__ float sm[];
    unsigned* sW1H = (unsigned*)(sm + EDGE_SW1);
    unsigned* sW2H = (unsigned*)(sm + EDGE_SW2);
    float*    sBuf = sm + EDGE_BUF;
    float*    sB1  = sm + EDGE_B1;
    float*    sB2  = sm + EDGE_B2;

    int tid = threadIdx.x;
    int lane = tid & 31;
    int w = tid >> 5;
    int g = lane >> 2, t = lane & 3;
    int R0 = 16 * w;
    int g2 = lane >> 3, tx8 = lane & 7;

    for (int i = tid; i < 16 * 128; i += 256) {
        int r = i >> 7, c = i & 127;
        int f = c >> 1, which = c & 1;
        int kk = r >> 2, tt = r & 3;
        int pl = tt + 4 * which;
        int k0 = kk * 16 + 2 * pl;
        float lo1 = (k0 < 50) ? W1[f * 50 + k0] : 0.f;
        float hi1 = (k0 + 1 < 50) ? W1[f * 50 + k0 + 1] : 0.f;
        sW1H[r * 136 + 2 * f + which] = h2pk(lo1, hi1);
        float lo2 = W2[f * 64 + k0];
        float hi2 = W2[f * 64 + k0 + 1];
        sW2H[r * 136 + 2 * f + which] = h2pk(lo2, hi2);
    }
    if (tid < 64) { sB1[tid] = bias1[tid]; sB2[tid] = bias2[tid]; }
    for (int i = tid; i < 128 * 72; i += 256) sBuf[i] = 0.f;
    __syncthreads();

    int frow = lane >> 1, fhalf = lane & 1;
    int koff = fhalf ? 26 : 0;
    int ncp = fhalf ? 12 : 13;
    unsigned fdst = (unsigned)__cvta_generic_to_shared(sBuf)
                  + (unsigned)((R0 + frow) * 72 + koff) * 4u;

    if (blockIdx.x < N_TILES) {
        int nid = __ldg(&g_meta[blockIdx.x * 128 + R0 + frow].w);
        const float* src = EA + (size_t)nid * NG + koff;
        for (int q = 0; q < ncp; q++)
            cp8(fdst + (unsigned)q * 8u, src + 2 * q);
    }
    cp_commit();

    for (int tile = blockIdx.x; tile < N_TILES; tile += EDGE_GRID) {
        int e0 = tile * 128;

        // ---- hoisted meta loads + NEXT tile's id + L2 prefetch ----
        int4 mt[4];
#pragma unroll
        for (int j = 0; j < 4; j++)
            mt[j] = __ldg(&g_meta[e0 + R0 + 4 * g2 + j]);

        int ntile = tile + EDGE_GRID;
        int nnid = 0;
        if (ntile < N_TILES) {
            nnid = __ldg(&g_meta[ntile * 128 + R0 + frow].w);
            const char* p = (const char*)(EA + (size_t)nnid * NG + koff);
            prefetchL2(p);
            prefetchL2(p + 96);
        }

        cp_wait0();
        __syncwarp();

        float c[8][4];
#pragma unroll
        for (int nb = 0; nb < 8; nb++)
#pragma unroll
            for (int q = 0; q < 4; q++) c[nb][q] = 0.f;

#pragma unroll
        for (int kk = 0; kk < 4; kk++) {
            int kb = kk * 16;
            float2 fa0 = *(const float2*)&sBuf[(R0 + g) * 72 + kb + 2 * t];
            float2 fa1 = *(const float2*)&sBuf[(R0 + g + 8) * 72 + kb + 2 * t];
            float2 fa2 = *(const float2*)&sBuf[(R0 + g) * 72 + kb + 2 * t + 8];
            float2 fa3 = *(const float2*)&sBuf[(R0 + g + 8) * 72 + kb + 2 * t + 8];
            unsigned a0 = h2pk(fa0.x, fa0.y);
            unsigned a1 = h2pk(fa1.x, fa1.y);
            unsigned a2 = h2pk(fa2.x, fa2.y);
            unsigned a3 = h2pk(fa3.x, fa3.y);
            const unsigned* brow = sW1H + (kk * 4 + t) * 136;
#pragma unroll
            for (int nb = 0; nb < 8; nb++) {
                uint2 bv = *(const uint2*)&brow[2 * (nb * 8 + g)];
                mma_f16(c[nb][0], c[nb][1], c[nb][2], c[nb][3],
                        a0, a1, a2, a3, bv.x, bv.y);
            }
        }

        unsigned ah[4][4];
#pragma unroll
        for (int kk = 0; kk < 4; kk++) {
            int cl = 16 * kk + 2 * t;
            float b00 = sB1[cl], b01 = sB1[cl + 1];
            float b10 = sB1[cl + 8], b11 = sB1[cl + 9];
            ah[kk][0] = h2pk(sspf(c[2 * kk][0] + b00), sspf(c[2 * kk][1] + b01));
            ah[kk][1] = h2pk(sspf(c[2 * kk][2] + b00), sspf(c[2 * kk][3] + b01));
            ah[kk][2] = h2pk(sspf(c[2 * kk + 1][0] + b10), sspf(c[2 * kk + 1][1] + b11));
            ah[kk][3] = h2pk(sspf(c[2 * kk + 1][2] + b10), sspf(c[2 * kk + 1][3] + b11));
        }

        float d[8][4];
#pragma unroll
        for (int nb = 0; nb < 8; nb++)
#pragma unroll
            for (int q = 0; q < 4; q++) d[nb][q] = 0.f;

#pragma unroll
        for (int kk = 0; kk < 4; kk++) {
            const unsigned* brow = sW2H + (kk * 4 + t) * 136;
#pragma unroll
            for (int nb = 0; nb < 8; nb++) {
                uint2 bv = *(const uint2*)&brow[2 * (nb * 8 + g)];
                mma_f16(d[nb][0], d[nb][1], d[nb][2], d[nb][3],
                        ah[kk][0], ah[kk][1], ah[kk][2], ah[kk][3], bv.x, bv.y);
            }
        }

#pragma unroll
        for (int nb = 0; nb < 8; nb++) {
            int col = nb * 8 + 2 * t;
            *(float2*)&sBuf[(R0 + g) * 72 + col] = make_float2(d[nb][0], d[nb][1]);
            *(float2*)&sBuf[(R0 + g + 8) * 72 + col] = make_float2(d[nb][2], d[nb][3]);
        }

        float4 h0[4], h1[4];
#pragma unroll
        for (int j = 0; j < 4; j++) {
            const float* hp = g_h + (size_t)mt[j].x * D1 + 8 * tx8;
            h0[j] = *(const float4*)hp;
            h1[j] = *(const float4*)(hp + 4);
        }
        __syncwarp();

        {
            float4 bb0 = *(const float4*)&sB2[8 * tx8];
            float4 bb1 = *(const float4*)&sB2[8 * tx8 + 4];
            int cur = -1;
            float4 r0 = make_float4(0.f, 0.f, 0.f, 0.f);
            float4 r1 = make_float4(0.f, 0.f, 0.f, 0.f);
#pragma unroll
            for (int j = 0; j < 4; j++) {
                int le = R0 + 4 * g2 + j;
                float cc = __int_as_float(mt[j].z);
                int dn = mt[j].y;
                float4 w0 = *(const float4*)&sBuf[le * 72 + 8 * tx8];
                float4 w1 = *(const float4*)&sBuf[le * 72 + 8 * tx8 + 4];
                float4 m0, m1;
                m0.x = (w0.x + bb0.x) * cc * h0[j].x;
                m0.y = (w0.y + bb0.y) * cc * h0[j].y;
                m0.z = (w0.z + bb0.z) * cc * h0[j].z;
                m0.w = (w0.w + bb0.w) * cc * h0[j].w;
                m1.x = (w1.x + bb1.x) * cc * h1[j].x;
                m1.y = (w1.y + bb1.y) * cc * h1[j].y;
                m1.z = (w1.z + bb1.z) * cc * h1[j].z;
                m1.w = (w1.w + bb1.w) * cc * h1[j].w;
                if (j == 0) {
                    cur = dn; r0 = m0; r1 = m1;
                } else if (dn == cur) {
                    r0.x += m0.x; r0.y += m0.y; r0.z += m0.z; r0.w += m0.w;
                    r1.x += m1.x; r1.y += m1.y; r1.z += m1.z; r1.w += m1.w;
                } else {
                    red4(&g_agg[(size_t)cur * D1 + 8 * tx8], r0);
                    red4(&g_agg[(size_t)cur * D1 + 8 * tx8 + 4], r1);
                    cur = dn; r0 = m0; r1 = m1;
                }
            }
            red4(&g_agg[(size_t)cur * D1 + 8 * tx8], r0);
            red4(&g_agg[(size_t)cur * D1 + 8 * tx8 + 4], r1);
        }
        __syncwarp();

        // ---- late fill from (now L2-resident) EA rows ----
        {
            if (ntile < N_TILES) {
                const float* src = EA + (size_t)nnid * NG + koff;
                for (int q = 0; q < ncp; q++)
                    cp8(fdst + (unsigned)q * 8u, src + 2 * q);
                if (fhalf) {
                    float* zrow = &sBuf[(R0 + frow) * 72];
#pragma unroll
                    for (int q = 0; q < 7; q++)
                        *(float2*)&zrow[50 + 2 * q] = make_float2(0.f, 0.f);
                }
            }
            cp_commit();
        }
    }
}

// =====================================================================
// k_node v2 (unchanged from R15)
// =====================================================================
#define NODE_SW1   0
#define NODE_SW2   2176
#define NODE_BUF   4352
#define NODE_BA    13568
#define NODE_BB    13632
#define NODE_SUM   13696
#define NODE_SQ    13760
#define NODE_SMEM_WORDS 13824
#define NODE_SMEM (NODE_SMEM_WORDS * 4)

__global__ __launch_bounds__(256, 3) void k_node(const float* __restrict__ Wa,
                                                 const float* __restrict__ ba,
                                                 const float* __restrict__ Wb,
                                                 const float* __restrict__ bb) {
    extern __shared__ float sm[];
    unsigned* sWaH = (unsigned*)(sm + NODE_SW1);
    unsigned* sWbH = (unsigned*)(sm + NODE_SW2);
    float*    sBuf = sm + NODE_BUF;
    float*    sBa  = sm + NODE_BA;
    float*    sBb  = sm + NODE_BB;
    float*    sSum = sm + NODE_SUM;
    float*    sSq  = sm + NODE_SQ;

    int tid = threadIdx.x;
    int lane = tid & 31;
    int w = tid >> 5;
    int g = lane >> 2, t = lane & 3;
    int R0 = 16 * w;
    int n0 = blockIdx.x * 128;

    for (int i = tid; i < 16 * 128; i += 256) {
        int r = i >> 7, c = i & 127;
        int f = c >> 1, which = c & 1;
        int kk = r >> 2, tt = r & 3;
        int pl = tt + 4 * which;
        int k0 = kk * 16 + 2 * pl;
        sWaH[r * 136 + 2 * f + which] = h2pk(Wa[f * 64 + k0], Wa[f * 64 + k0 + 1]);
        sWbH[r * 136 + 2 * f + which] = h2pk(Wb[f * 64 + k0], Wb[f * 64 + k0 + 1]);
    }
    if (tid < 64) { sBa[tid] = ba[tid]; sBb[tid] = bb[tid]; sSum[tid] = 0.f; sSq[tid] = 0.f; }
    __syncthreads();

#pragma unroll
    for (int r = 0; r < 16; r++) {
        int n = n0 + R0 + r;
        float2 v = make_float2(0.f, 0.f);
        if (n < N_NODES) v = *(const float2*)&g_agg[(size_t)n * D1 + 2 * lane];
        *(float2*)&sBuf[(R0 + r) * 72 + 2 * lane] = v;
    }
    __syncwarp();

    float c[8][4];
#pragma unroll
    for (int nb = 0; nb < 8; nb++)
#pragma unroll
        for (int q = 0; q < 4; q++) c[nb][q] = 0.f;

#pragma unroll
    for (int kk = 0; kk < 4; kk++) {
        int kb = kk * 16;
        float2 fa0 = *(const float2*)&sBuf[(R0 + g) * 72 + kb + 2 * t];
        float2 fa1 = *(const float2*)&sBuf[(R0 + g + 8) * 72 + kb + 2 * t];
        float2 fa2 = *(const float2*)&sBuf[(R0 + g) * 72 + kb + 2 * t + 8];
        float2 fa3 = *(const float2*)&sBuf[(R0 + g + 8) * 72 + kb + 2 * t + 8];
        unsigned a0 = h2pk(fa0.x, fa0.y);
        unsigned a1 = h2pk(fa1.x, fa1.y);
        unsigned a2 = h2pk(fa2.x, fa2.y);
        unsigned a3 = h2pk(fa3.x, fa3.y);
        const unsigned* brow = sWaH + (kk * 4 + t) * 136;
#pragma unroll
        for (int nb = 0; nb < 8; nb++) {
            uint2 bv = *(const uint2*)&brow[2 * (nb * 8 + g)];
            mma_f16(c[nb][0], c[nb][1], c[nb][2], c[nb][3],
                    a0, a1, a2, a3, bv.x, bv.y);
        }
    }

    unsigned ah[4][4];
#pragma unroll
    for (int kk = 0; kk < 4; kk++) {
        int cl = 16 * kk + 2 * t;
        float b00 = sBa[cl], b01 = sBa[cl + 1];
        float b10 = sBa[cl + 8], b11 = sBa[cl + 9];
        ah[kk][0] = h2pk(sspf(c[2 * kk][0] + b00), sspf(c[2 * kk][1] + b01));
        ah[kk][1] = h2pk(sspf(c[2 * kk][2] + b00), sspf(c[2 * kk][3] + b01));
        ah[kk][2] = h2pk(sspf(c[2 * kk + 1][0] + b10), sspf(c[2 * kk + 1][1] + b11));
        ah[kk][3] = h2pk(sspf(c[2 * kk + 1][2] + b10), sspf(c[2 * kk + 1][3] + b11));
    }

    float d[8][4];
#pragma unroll
    for (int nb = 0; nb < 8; nb++)
#pragma unroll
        for (int q = 0; q < 4; q++) d[nb][q] = 0.f;

#pragma unroll
    for (int kk = 0; kk < 4; kk++) {
        const unsigned* brow = sWbH + (kk * 4 + t) * 136;
#pragma unroll
        for (int nb = 0; nb < 8; nb++) {
            uint2 bv = *(const uint2*)&brow[2 * (nb * 8 + g)];
            mma_f16(d[nb][0], d[nb][1], d[nb][2], d[nb][3],
                    ah[kk][0], ah[kk][1], ah[kk][2], ah[kk][3], bv.x, bv.y);
        }
    }

    int nA = n0 + R0 + g;
    int nB = n0 + R0 + g + 8;
#pragma unroll
    for (int nb = 0; nb < 8; nb++) {
        int col = nb * 8 + 2 * t;
        float b0 = sBb[col], b1 = sBb[col + 1];
        float2 rA = make_float2(0.f, 0.f), rB = make_float2(0.f, 0.f);
        if (nA < N_NODES) {
            float2 prev = *(const float2*)&g_out[(size_t)nA * D1 + col];
            rA.x = d[nb][0] + b0 + prev.x;
            rA.y = d[nb][1] + b1 + prev.y;
            *(float2*)&g_out[(size_t)nA * D1 + col] = rA;
        }
        if (nB < N_NODES) {
            float2 prev = *(const float2*)&g_out[(size_t)nB * D1 + col];
            rB.x = d[nb][2] + b0 + prev.x;
            rB.y = d[nb][3] + b1 + prev.y;
            *(float2*)&g_out[(size_t)nB * D1 + col] = rB;
        }
        *(float2*)&sBuf[(R0 + g) * 72 + col] = rA;
        *(float2*)&sBuf[(R0 + g + 8) * 72 + col] = rB;
    }
    __syncthreads();

    {
        int col = tid & 63, q = tid >> 6;
        float ps = 0.f, pq = 0.f;
        for (int r = 32 * q; r < 32 * q + 32; r++) {
            float v = sBuf[r * 72 + col];
            ps += v;
            pq += v * v;
        }
        atomicAdd(&sSum[col], ps);
        atomicAdd(&sSq[col], pq);
    }
    __syncthreads();
    if (tid < 64) {
        atomicAdd(&g_bnstats[tid], sSum[tid]);
        atomicAdd(&g_bnstats[64 + tid], sSq[tid]);
    }
}

// =====================================================================
// pool with fused layer-2 BN
// =====================================================================
__global__ __launch_bounds__(256) void k_pool(const int* __restrict__ batch,
                                              const float* __restrict__ bng,
                                              const float* __restrict__ bnb) {
    __shared__ float sSc[64], sOf[64];
    int tid = threadIdx.x;
    if (tid < 64) {
        const float invN = 1.f / (float)N_NODES;
        float mu = g_bnstats[tid] * invN;
        float var = fmaxf(g_bnstats[64 + tid] * invN - mu * mu, 0.f);
        float sc = rsqrtf(var + BN_EPS) * bng[tid];
        sSc[tid] = sc;
        sOf[tid] = bnb[tid] - mu * sc;
    }
    __syncthreads();
    int idx = blockIdx.x * blockDim.x + tid;
    if (idx >= N_NODES * D1) return;
    int n = idx >> 6, f = idx & 63;
    int bg = batch[n];
    float v = g_out[idx] * sSc[f] + sOf[f];
    atomicAdd(&g_pool[bg * D1 + f], v);
    if (f == 0) atomicAdd(&g_cnt[bg], 1.f);
}

__global__ void k_head(const float* __restrict__ postW, const float* __restrict__ postb,
                       const float* __restrict__ outW, const float* __restrict__ outb,
                       float* __restrict__ y) {
    int g = blockIdx.x;
    int f = threadIdx.x;
    __shared__ float sp[64];
    __shared__ float sr[2];
    float cnt = fmaxf(g_cnt[g], 1.f);
    sp[f] = g_pool[g * D1 + f] / cnt;
    __syncthreads();
    float a = postb[f];
#pragma unroll
    for (int k = 0; k < 64; k++) a = fmaf(sp[k], postW[f * 64 + k], a);
    float hp = fmaxf(a, 0.f) * outW[f];
#pragma unroll
    for (int o = 16; o > 0; o >>= 1) hp += __shfl_down_sync(0xffffffffu, hp, o);
    if ((f & 31) == 0) sr[f >> 5] = hp;
    __syncthreads();
    if (f == 0) y[g] = sr[0] + sr[1] + outb[0];
}

// =====================================================================
extern "C" void kernel_launch(void* const* d_in, const int* in_sizes, int n_in,
                              void* d_out, int out_size) {
    const float* x      = (const float*)d_in[0];
    const float* ew     = (const float*)d_in[1];
    const float* ea     = (const float*)d_in[2];
    const int*   ei     = (const int*)d_in[3];
    const int*   batch  = (const int*)d_in[4];
    const float* pre_W  = (const float*)d_in[5];
    const float* pre_b  = (const float*)d_in[6];
    const float* mlp_W1 = (const float*)d_in[7];
    const float* mlp_b1 = (const float*)d_in[8];
    const float* mlp_W2 = (const float*)d_in[9];
    const float* mlp_b2 = (const float*)d_in[10];
    const float* cf_W1  = (const float*)d_in[11];
    const float* cf_W2  = (const float*)d_in[12];
    const float* cf_b2  = (const float*)d_in[13];
    const float* int_W  = (const float*)d_in[14];
    const float* int_b  = (const float*)d_in[15];
    const float* bn_g   = (const float*)d_in[16];
    const float* bn_b   = (const float*)d_in[17];
    const float* post_W = (const float*)d_in[18];
    const float* post_b = (const float*)d_in[19];
    const float* out_W  = (const float*)d_in[20];
    const float* out_b  = (const float*)d_in[21];
    float* y = (float*)d_out;

    void *agg_p, *bn_p, *pool_p, *cnt_p, *hist_p;
    cudaGetSymbolAddress(&agg_p, g_agg);
    cudaGetSymbolAddress(&bn_p, g_bnstats);
    cudaGetSymbolAddress(&pool_p, g_pool);
    cudaGetSymbolAddress(&cnt_p, g_cnt);
    cudaGetSymbolAddress(&hist_p, g_hist);

    cudaFuncSetAttribute(k_edge, cudaFuncAttributeMaxDynamicSharedMemorySize, EDGE_SMEM);
    cudaFuncSetAttribute(k_node, cudaFuncAttributeMaxDynamicSharedMemorySize, NODE_SMEM);
    cudaFuncSetAttribute(k_lin1, cudaFuncAttributeMaxDynamicSharedMemorySize, LIN1_SMEM);
    cudaFuncSetAttribute(k_pre, cudaFuncAttributeMaxDynamicSharedMemorySize, PRE_SMEM);

    // counting sort of edges by dst (scatter writes packed sorted meta)
    cudaMemsetAsync(hist_p, 0, N_NODES * sizeof(int));
    k_hist<<<(N_EDGES + 255) / 256, 256>>>(ei);
    k_scan<<<1, 1024>>>();
    k_scatter<<<(N_EDGES + 255) / 256, 256>>>(ei, ew);

    k_pre<<<(N_NODES + 127) / 128, 256, PRE_SMEM>>>(x, pre_W, pre_b);
    cudaMemsetAsync(pool_p, 0, N_GRAPHS * D1 * sizeof(float));
    cudaMemsetAsync(cnt_p, 0, N_GRAPHS * sizeof(float));

    for (int l = 0; l < 3; l++) {
        k_lin1<<<(N_NODES + 127) / 128, 256, LIN1_SMEM>>>(
            cf_W1 + l * 64 * 64,
            bn_g + (l > 0 ? (l - 1) * 64 : 0),
            bn_b + (l > 0 ? (l - 1) * 64 : 0),
            l > 0 ? 1 : 0);
        cudaMemsetAsync(agg_p, 0, (size_t)N_NODES * D1 * sizeof(float));
        cudaMemsetAsync(bn_p, 0, 2 * D1 * sizeof(float));
        k_edge<<<EDGE_GRID, 256, EDGE_SMEM>>>(ea,
                                              mlp_W1 + l * 64 * 50, mlp_b1 + l * 64,
                                              mlp_W2 + l * 64 * 64, mlp_b2 + l * 64);
        k_node<<<(N_NODES + 127) / 128, 256, NODE_SMEM>>>(cf_W2 + l * 64 * 64, cf_b2 + l * 64,
                                                          int_W + l * 64 * 64, int_b + l * 64);
    }

    k_pool<<<(N_NODES * D1 + 255) / 256, 256>>>(batch, bn_g + 2 * 64, bn_b + 2 * 64);
    k_head<<<N_GRAPHS, 64>>>(post_W, post_b, out_W, out_b, y);
}

// round 17
// speedup vs baseline: 1.0131x; 1.0131x over previous
#include <cuda_runtime.h>
#include <math_constants.h>

#define N_NODES 50000
#define N_EDGES 1200000
#define N_GRAPHS 512
#define D1 64
#define NF 92
#define NG 50
#define BN_EPS 1e-5f
#define LOG2F_C 0.6931471805599453f

#define N_TILES (N_EDGES / 128)   // 9375
#define EDGE_GRID 444             // 3 CTAs/SM * 148

typedef unsigned long long ull;

// -------------------- device scratch --------------------
__device__ float g_out[N_NODES * D1];
__device__ float g_h[N_NODES * D1];
__device__ float g_agg[N_NODES * D1];
__device__ float g_bnstats[2 * D1];
__device__ float g_pool[N_GRAPHS * D1];
__device__ float g_cnt[N_GRAPHS];
__device__ int   g_hist[N_NODES];
__device__ int4  g_meta[N_EDGES];   // {src, dst, C-bits, orig edge id}, dst-sorted

// -------------------- helpers --------------------
__device__ __forceinline__ ull ffma2(ull a, ull b, ull c) {
    ull d;
    asm("fma.rn.f32x2 %0, %1, %2, %3;" : "=l"(d) : "l"(a), "l"(b), "l"(c));
    return d;
}
__device__ __forceinline__ ull dup2(float v) {
    ull r;
    asm("mov.b64 %0, {%1, %1};" : "=l"(r) : "f"(v));
    return r;
}
__device__ __forceinline__ float f2lo(ull v) { return __uint_as_float((unsigned)(v & 0xffffffffull)); }
__device__ __forceinline__ float f2hi(ull v) { return __uint_as_float((unsigned)(v >> 32)); }

__device__ __forceinline__ float sspf(float v) {
    return fmaxf(v, 0.f) + __logf(1.f + __expf(-fabsf(v))) - LOG2F_C;
}

__device__ __forceinline__ void red4(float* p, float4 v) {
    asm volatile("red.global.add.v4.f32 [%0], {%1,%2,%3,%4};"
                 :: "l"(p), "f"(v.x), "f"(v.y), "f"(v.z), "f"(v.w) : "memory");
}

__device__ __forceinline__ void cp8(unsigned dst, const void* src) {
    asm volatile("cp.async.ca.shared.global [%0], [%1], 8;" :: "r"(dst), "l"(src));
}
__device__ __forceinline__ void cp_commit() {
    asm volatile("cp.async.commit_group;" ::: "memory");
}
__device__ __forceinline__ void cp_wait0() {
    asm volatile("cp.async.wait_group 0;" ::: "memory");
}
// pack two f32 -> f16x2 (lo = first arg)
__device__ __forceinline__ unsigned h2pk(float lo, float hi) {
    unsigned d;
    asm("cvt.rn.f16x2.f32 %0, %1, %2;" : "=r"(d) : "f"(hi), "f"(lo));
    return d;
}
__device__ __forceinline__ void mma_f16(float& c0, float& c1, float& c2, float& c3,
                                        unsigned a0, unsigned a1, unsigned a2, unsigned a3,
                                        unsigned b0, unsigned b1) {
    asm volatile("mma.sync.aligned.m16n8k16.row.col.f32.f16.f16.f32 "
                 "{%0,%1,%2,%3}, {%4,%5,%6,%7}, {%8,%9}, {%0,%1,%2,%3};"
                 : "+f"(c0), "+f"(c1), "+f"(c2), "+f"(c3)
                 : "r"(a0), "r"(a1), "r"(a2), "r"(a3), "r"(b0), "r"(b1));
}

// =====================================================================
// counting sort by dst; scatter materializes packed sorted meta
// =====================================================================
__global__ void k_hist(const int* __restrict__ ei) {
    int i = blockIdx.x * blockDim.x + threadIdx.x;
    if (i < N_EDGES) atomicAdd(&g_hist[ei[N_EDGES + i]], 1);
}

__global__ __launch_bounds__(1024) void k_scan() {
    __shared__ int ss[1024];
    int t = threadIdx.x;
    int lo = t * 49;
    int hi = min(lo + 49, N_NODES);
    int s = 0;
    for (int b = lo; b < hi; b++) s += g_hist[b];
    ss[t] = s;
    __syncthreads();
    for (int off = 1; off < 1024; off <<= 1) {
        int v = (t >= off) ? ss[t - off] : 0;
        __syncthreads();
        ss[t] += v;
        __syncthreads();
    }
    int run = ss[t] - s;
    for (int b = lo; b < hi; b++) {
        int c = g_hist[b];
        g_hist[b] = run;
        run += c;
    }
}

__global__ void k_scatter(const int* __restrict__ ei, const float* __restrict__ ew) {
    int i = blockIdx.x * blockDim.x + threadIdx.x;
    if (i < N_EDGES) {
        int dst = ei[N_EDGES + i];
        int pos = atomicAdd(&g_hist[dst], 1);
        int4 m;
        m.x = ei[i];
        m.y = dst;
        m.z = __float_as_int(0.5f * (cospif(ew[i] * 0.125f) + 1.f));
        m.w = i;
        g_meta[pos] = m;
    }
}

// =====================================================================
// pre FC (block-tile f32x2 GEMM, 128-node tiles, 3 CTAs/SM: one wave)
// =====================================================================
#define PRE_SMEM ((5888 + 12032 + 64) * 4)
__global__ __launch_bounds__(256, 3) void k_pre(const float* __restrict__ x,
                                                const float* __restrict__ W,
                                                const float* __restrict__ b) {
    extern __shared__ float sm[];
    float* sWt = sm;            // [92][64] k-major
    float* sA = sm + 5888;      // [128][94]
    float* sB = sm + 17920;     // [64]

    int tid = threadIdx.x;
    int tx = tid & 7, ty = tid >> 3;
    int n0 = blockIdx.x * 128;

    for (int i = tid; i < 92 * 64; i += 256) {
        int f = i / 92, k = i - f * 92;
        sWt[k * 64 + f] = W[i];
    }
    if (tid < 64) sB[tid] = b[tid];
    for (int i = tid; i < 128 * 92; i += 256) {
        int r = i / 92, k = i - r * 92;
        int n = n0 + r;
        sA[r * 94 + k] = (n < N_NODES) ? x[(size_t)n * NF + k] : 0.f;
    }
    __syncthreads();

    ull acc[4][4];
#pragma unroll
    for (int j = 0; j < 4; j++)
#pragma unroll
        for (int p = 0; p < 4; p++) acc[j][p] = 0ull;

#pragma unroll 4
    for (int k = 0; k < 92; k++) {
        ulonglong2 bA = *(const ulonglong2*)&sWt[k * 64 + 8 * tx];
        ulonglong2 bB = *(const ulonglong2*)&sWt[k * 64 + 8 * tx + 4];
#pragma unroll
        for (int j = 0; j < 4; j++) {
            ull av = dup2(sA[(4 * ty + j) * 94 + k]);
            acc[j][0] = ffma2(av, bA.x, acc[j][0]);
            acc[j][1] = ffma2(av, bA.y, acc[j][1]);
            acc[j][2] = ffma2(av, bB.x, acc[j][2]);
            acc[j][3] = ffma2(av, bB.y, acc[j][3]);
        }
    }

#pragma unroll
    for (int j = 0; j < 4; j++) {
        int n = n0 + 4 * ty + j;
        if (n < N_NODES) {
            float4 o0, o1;
            o0.x = fmaxf(f2lo(acc[j][0]) + sB[8 * tx + 0], 0.f);
            o0.y = fmaxf(f2hi(acc[j][0]) + sB[8 * tx + 1], 0.f);
            o0.z = fmaxf(f2lo(acc[j][1]) + sB[8 * tx + 2], 0.f);
            o0.w = fmaxf(f2hi(acc[j][1]) + sB[8 * tx + 3], 0.f);
            o1.x = fmaxf(f2lo(acc[j][2]) + sB[8 * tx + 4], 0.f);
            o1.y = fmaxf(f2hi(acc[j][2]) + sB[8 * tx + 5], 0.f);
            o1.z = fmaxf(f2lo(acc[j][3]) + sB[8 * tx + 6], 0.f);
            o1.w = fmaxf(f2hi(acc[j][3]) + sB[8 * tx + 7], 0.f);
            *(float4*)&g_out[(size_t)n * D1 + 8 * tx] = o0;
            *(float4*)&g_out[(size_t)n * D1 + 8 * tx + 4] = o1;
        }
    }
}

// =====================================================================
// lin1 (+ fused BN of previous layer) — R15 version (fp32, block-tile)
// =====================================================================
#define LIN1_SMEM ((4096 + 16384 + 192) * 4)
__global__ __launch_bounds__(256, 2) void k_lin1(const float* __restrict__ W,
                                                 const float* __restrict__ bng,
                                                 const float* __restrict__ bnb,
                                                 int apply_bn) {
    extern __shared__ float sm[];
    float* sWt = sm;
    float* sA = sm + 4096;
    float* sSc = sm + 20480;
    float* sOf = sSc + 64;

    int tid = threadIdx.x;
    int tx = tid & 15, ty = tid >> 4;
    int n0 = blockIdx.x * 128;

    for (int i = tid; i < 64 * 64; i += 256) {
        int f = i >> 6, k = i & 63;
        sWt[k * 64 + f] = W[i];
    }
    if (tid < 64 && apply_bn) {
        const float invN = 1.f / (float)N_NODES;
        float mu = g_bnstats[tid] * invN;
        float var = fmaxf(g_bnstats[64 + tid] * invN - mu * mu, 0.f);
        float sc = rsqrtf(var + BN_EPS) * bng[tid];
        sSc[tid] = sc;
        sOf[tid] = bnb[tid] - mu * sc;
    }
    __syncthreads();

    for (int i = tid; i < 128 * 64; i += 256) {
        int e = i >> 6, k = i & 63;
        int n = n0 + e;
        float v = 0.f;
        if (n < N_NODES) {
            v = g_out[n * D1 + k];
            if (apply_bn) {
                v = v * sSc[k] + sOf[k];
                g_out[n * D1 + k] = v;
            }
        }
        *(float2*)&sA[e * 128 + 2 * k] = make_float2(v, v);
    }
    __syncthreads();

    ull acc[8][2];
#pragma unroll
    for (int ii = 0; ii < 8; ii++) { acc[ii][0] = 0ull; acc[ii][1] = 0ull; }
#pragma unroll
    for (int p = 0; p < 32; p++) {
        ulonglong2 b0 = *reinterpret_cast<const ulonglong2*>(&sWt[(2 * p) * 64 + 4 * tx]);
        ulonglong2 b1 = *reinterpret_cast<const ulonglong2*>(&sWt[(2 * p + 1) * 64 + 4 * tx]);
#pragma unroll
        for (int ii = 0; ii < 8; ii++) {
            ulonglong2 a = *reinterpret_cast<const ulonglong2*>(&sA[(ty + 16 * ii) * 128 + 4 * p]);
            acc[ii][0] = ffma2(a.x, b0.x, acc[ii][0]);
            acc[ii][1] = ffma2(a.x, b0.y, acc[ii][1]);
            acc[ii][0] = ffma2(a.y, b1.x, acc[ii][0]);
            acc[ii][1] = ffma2(a.y, b1.y, acc[ii][1]);
        }
    }
#pragma unroll
    for (int ii = 0; ii < 8; ii++) {
        int n = n0 + ty + 16 * ii;
        if (n < N_NODES) {
            float4 o;
            o.x = f2lo(acc[ii][0]); o.y = f2hi(acc[ii][0]);
            o.z = f2lo(acc[ii][1]); o.w = f2hi(acc[ii][1]);
            *(float4*)&g_h[n * D1 + 4 * tx] = o;
        }
    }
}

// =====================================================================
// k_edge v12 (R15 version, unchanged)
// =====================================================================
#define EDGE_SW1   0                  // uint [16][136] = 2176
#define EDGE_SW2   2176               // uint [16][136] = 2176
#define EDGE_BUF   4352               // float [128][72] = 9216
#define EDGE_B1    13568
#define EDGE_B2    13632
#define EDGE_SMEM_WORDS 13696
#define EDGE_SMEM (EDGE_SMEM_WORDS * 4)

__global__ __launch_bounds__(256, 3) void k_edge(const float* __restrict__ EA,
                                                 const float* __restrict__ W1,
                                                 const float* __restrict__ bias1,
                                                 const float* __restrict__ W2,
                                                 const float* __restrict__ bias2) {
    extern __shared__ float sm[];
    unsigned* sW1H = (unsigned*)(sm + EDGE_SW1);
    unsigned* sW2H = (unsigned*)(sm + EDGE_SW2);
    float*    sBuf = sm + EDGE_BUF;
    float*    sB1  = sm + EDGE_B1;
    float*    sB2  = sm + EDGE_B2;

    int tid = threadIdx.x;
    int lane = tid & 31;
    int w = tid >> 5;
    int g = lane >> 2, t = lane & 3;
    int R0 = 16 * w;
    int g2 = lane >> 3, tx8 = lane & 7;

    for (int i = tid; i < 16 * 128; i += 256) {
        int r = i >> 7, c = i & 127;
        int f = c >> 1, which = c & 1;
        int kk = r >> 2, tt = r & 3;
        int pl = tt + 4 * which;
        int k0 = kk * 16 + 2 * pl;
        float lo1 = (k0 < 50) ? W1[f * 50 + k0] : 0.f;
        float hi1 = (k0 + 1 < 50) ? W1[f * 50 + k0 + 1] : 0.f;
        sW1H[r * 136 + 2 * f + which] = h2pk(lo1, hi1);
        float lo2 = W2[f * 64 + k0];
        float hi2 = W2[f * 64 + k0 + 1];
        sW2H[r * 136 + 2 * f + which] = h2pk(lo2, hi2);
    }
    if (tid < 64) { sB1[tid] = bias1[tid]; sB2[tid] = bias2[tid]; }
    for (int i = tid; i < 128 * 72; i += 256) sBuf[i] = 0.f;
    __syncthreads();

    int frow = lane >> 1, fhalf = lane & 1;
    int koff = fhalf ? 26 : 0;
    int ncp = fhalf ? 12 : 13;
    unsigned fdst = (unsigned)__cvta_generic_to_shared(sBuf)
                  + (unsigned)((R0 + frow) * 72 + koff) * 4u;

    if (blockIdx.x < N_TILES) {
        int nid = __ldg(&g_meta[blockIdx.x * 128 + R0 + frow].w);
        const float* src = EA + (size_t)nid * NG + koff;
        for (int q = 0; q < ncp; q++)
            cp8(fdst + (unsigned)q * 8u, src + 2 * q);
    }
    cp_commit();

    for (int tile = blockIdx.x; tile < N_TILES; tile += EDGE_GRID) {
        int e0 = tile * 128;

        int4 mt[4];
#pragma unroll
        for (int j = 0; j < 4; j++)
            mt[j] = __ldg(&g_meta[e0 + R0 + 4 * g2 + j]);

        cp_wait0();
        __syncwarp();

        float c[8][4];
#pragma unroll
        for (int nb = 0; nb < 8; nb++)
#pragma unroll
            for (int q = 0; q < 4; q++) c[nb][q] = 0.f;

#pragma unroll
        for (int kk = 0; kk < 4; kk++) {
            int kb = kk * 16;
            float2 fa0 = *(const float2*)&sBuf[(R0 + g) * 72 + kb + 2 * t];
            float2 fa1 = *(const float2*)&sBuf[(R0 + g + 8) * 72 + kb + 2 * t];
            float2 fa2 = *(const float2*)&sBuf[(R0 + g) * 72 + kb + 2 * t + 8];
            float2 fa3 = *(const float2*)&sBuf[(R0 + g + 8) * 72 + kb + 2 * t + 8];
            unsigned a0 = h2pk(fa0.x, fa0.y);
            unsigned a1 = h2pk(fa1.x, fa1.y);
            unsigned a2 = h2pk(fa2.x, fa2.y);
            unsigned a3 = h2pk(fa3.x, fa3.y);
            const unsigned* brow = sW1H + (kk * 4 + t) * 136;
#pragma unroll
            for (int nb = 0; nb < 8; nb++) {
                uint2 bv = *(const uint2*)&brow[2 * (nb * 8 + g)];
                mma_f16(c[nb][0], c[nb][1], c[nb][2], c[nb][3],
                        a0, a1, a2, a3, bv.x, bv.y);
            }
        }

        unsigned ah[4][4];
#pragma unroll
        for (int kk = 0; kk < 4; kk++) {
            int cl = 16 * kk + 2 * t;
            float b00 = sB1[cl], b01 = sB1[cl + 1];
            float b10 = sB1[cl + 8], b11 = sB1[cl + 9];
            ah[kk][0] = h2pk(sspf(c[2 * kk][0] + b00), sspf(c[2 * kk][1] + b01));
            ah[kk][1] = h2pk(sspf(c[2 * kk][2] + b00), sspf(c[2 * kk][3] + b01));
            ah[kk][2] = h2pk(sspf(c[2 * kk + 1][0] + b10), sspf(c[2 * kk + 1][1] + b11));
            ah[kk][3] = h2pk(sspf(c[2 * kk + 1][2] + b10), sspf(c[2 * kk + 1][3] + b11));
        }

        float d[8][4];
#pragma unroll
        for (int nb = 0; nb < 8; nb++)
#pragma unroll
            for (int q = 0; q < 4; q++) d[nb][q] = 0.f;

#pragma unroll
        for (int kk = 0; kk < 4; kk++) {
            const unsigned* brow = sW2H + (kk * 4 + t) * 136;
#pragma unroll
            for (int nb = 0; nb < 8; nb++) {
                uint2 bv = *(const uint2*)&brow[2 * (nb * 8 + g)];
                mma_f16(d[nb][0], d[nb][1], d[nb][2], d[nb][3],
                        ah[kk][0], ah[kk][1], ah[kk][2], ah[kk][3], bv.x, bv.y);
            }
        }

#pragma unroll
        for (int nb = 0; nb < 8; nb++) {
            int col = nb * 8 + 2 * t;
            *(float2*)&sBuf[(R0 + g) * 72 + col] = make_float2(d[nb][0], d[nb][1]);
            *(float2*)&sBuf[(R0 + g + 8) * 72 + col] = make_float2(d[nb][2], d[nb][3]);
        }

        float4 h0[4], h1[4];
#pragma unroll
        for (int j = 0; j < 4; j++) {
            const float* hp = g_h + (size_t)mt[j].x * D1 + 8 * tx8;
            h0[j] = *(const float4*)hp;
            h1[j] = *(const float4*)(hp + 4);
        }
        __syncwarp();

        {
            float4 bb0 = *(const float4*)&sB2[8 * tx8];
            float4 bb1 = *(const float4*)&sB2[8 * tx8 + 4];
            int cur = -1;
            float4 r0 = make_float4(0.f, 0.f, 0.f, 0.f);
            float4 r1 = make_float4(0.f, 0.f, 0.f, 0.f);
#pragma unroll
            for (int j = 0; j < 4; j++) {
                int le = R0 + 4 * g2 + j;
                float cc = __int_as_float(mt[j].z);
                int dn = mt[j].y;
                float4 w0 = *(const float4*)&sBuf[le * 72 + 8 * tx8];
                float4 w1 = *(const float4*)&sBuf[le * 72 + 8 * tx8 + 4];
                float4 m0, m1;
                m0.x = (w0.x + bb0.x) * cc * h0[j].x;
                m0.y = (w0.y + bb0.y) * cc * h0[j].y;
                m0.z = (w0.z + bb0.z) * cc * h0[j].z;
                m0.w = (w0.w + bb0.w) * cc * h0[j].w;
                m1.x = (w1.x + bb1.x) * cc * h1[j].x;
                m1.y = (w1.y + bb1.y) * cc * h1[j].y;
                m1.z = (w1.z + bb1.z) * cc * h1[j].z;
                m1.w = (w1.w + bb1.w) * cc * h1[j].w;
                if (j == 0) {
                    cur = dn; r0 = m0; r1 = m1;
                } else if (dn == cur) {
                    r0.x += m0.x; r0.y += m0.y; r0.z += m0.z; r0.w += m0.w;
                    r1.x += m1.x; r1.y += m1.y; r1.z += m1.z; r1.w += m1.w;
                } else {
                    red4(&g_agg[(size_t)cur * D1 + 8 * tx8], r0);
                    red4(&g_agg[(size_t)cur * D1 + 8 * tx8 + 4], r1);
                    cur = dn; r0 = m0; r1 = m1;
                }
            }
            red4(&g_agg[(size_t)cur * D1 + 8 * tx8], r0);
            red4(&g_agg[(size_t)cur * D1 + 8 * tx8 + 4], r1);
        }
        __syncwarp();

        {
            int ntile = tile + EDGE_GRID;
            if (ntile < N_TILES) {
                int nid = __ldg(&g_meta[ntile * 128 + R0 + frow].w);
                const float* src = EA + (size_t)nid * NG + koff;
                for (int q = 0; q < ncp; q++)
                    cp8(fdst + (unsigned)q * 8u, src + 2 * q);
                if (fhalf) {
                    float* zrow = &sBuf[(R0 + frow) * 72];
#pragma unroll
                    for (int q = 0; q < 7; q++)
                        *(float2*)&zrow[50 + 2 * q] = make_float2(0.f, 0.f);
                }
            }
            cp_commit();
        }
    }
}

// =====================================================================
// k_node v2 (R15 version, unchanged)
// =====================================================================
#define NODE_SW1   0
#define NODE_SW2   2176
#define NODE_BUF   4352
#define NODE_BA    13568
#define NODE_BB    13632
#define NODE_SUM   13696
#define NODE_SQ    13760
#define NODE_SMEM_WORDS 13824
#define NODE_SMEM (NODE_SMEM_WORDS * 4)

__global__ __launch_bounds__(256, 3) void k_node(const float* __restrict__ Wa,
                                                 const float* __restrict__ ba,
                                                 const float* __restrict__ Wb,
                                                 const float* __restrict__ bb) {
    extern __shared__ float sm[];
    unsigned* sWaH = (unsigned*)(sm + NODE_SW1);
    unsigned* sWbH = (unsigned*)(sm + NODE_SW2);
    float*    sBuf = sm + NODE_BUF;
    float*    sBa  = sm + NODE_BA;
    float*    sBb  = sm + NODE_BB;
    float*    sSum = sm + NODE_SUM;
    float*    sSq  = sm + NODE_SQ;

    int tid = threadIdx.x;
    int lane = tid & 31;
    int w = tid >> 5;
    int g = lane >> 2, t = lane & 3;
    int R0 = 16 * w;
    int n0 = blockIdx.x * 128;

    for (int i = tid; i < 16 * 128; i += 256) {
        int r = i >> 7, c = i & 127;
        int f = c >> 1, which = c & 1;
        int kk = r >> 2, tt = r & 3;
        int pl = tt + 4 * which;
        int k0 = kk * 16 + 2 * pl;
        sWaH[r * 136 + 2 * f + which] = h2pk(Wa[f * 64 + k0], Wa[f * 64 + k0 + 1]);
        sWbH[r * 136 + 2 * f + which] = h2pk(Wb[f * 64 + k0], Wb[f * 64 + k0 + 1]);
    }
    if (tid < 64) { sBa[tid] = ba[tid]; sBb[tid] = bb[tid]; sSum[tid] = 0.f; sSq[tid] = 0.f; }
    __syncthreads();

#pragma unroll
    for (int r = 0; r < 16; r++) {
        int n = n0 + R0 + r;
        float2 v = make_float2(0.f, 0.f);
        if (n < N_NODES) v = *(const float2*)&g_agg[(size_t)n * D1 + 2 * lane];
        *(float2*)&sBuf[(R0 + r) * 72 + 2 * lane] = v;
    }
    __syncwarp();

    float c[8][4];
#pragma unroll
    for (int nb = 0; nb < 8; nb++)
#pragma unroll
        for (int q = 0; q < 4; q++) c[nb][q] = 0.f;

#pragma unroll
    for (int kk = 0; kk < 4; kk++) {
        int kb = kk * 16;
        float2 fa0 = *(const float2*)&sBuf[(R0 + g) * 72 + kb + 2 * t];
        float2 fa1 = *(const float2*)&sBuf[(R0 + g + 8) * 72 + kb + 2 * t];
        float2 fa2 = *(const float2*)&sBuf[(R0 + g) * 72 + kb + 2 * t + 8];
        float2 fa3 = *(const float2*)&sBuf[(R0 + g + 8) * 72 + kb + 2 * t + 8];
        unsigned a0 = h2pk(fa0.x, fa0.y);
        unsigned a1 = h2pk(fa1.x, fa1.y);
        unsigned a2 = h2pk(fa2.x, fa2.y);
        unsigned a3 = h2pk(fa3.x, fa3.y);
        const unsigned* brow = sWaH + (kk * 4 + t) * 136;
#pragma unroll
        for (int nb = 0; nb < 8; nb++) {
            uint2 bv = *(const uint2*)&brow[2 * (nb * 8 + g)];
            mma_f16(c[nb][0], c[nb][1], c[nb][2], c[nb][3],
                    a0, a1, a2, a3, bv.x, bv.y);
        }
    }

    unsigned ah[4][4];
#pragma unroll
    for (int kk = 0; kk < 4; kk++) {
        int cl = 16 * kk + 2 * t;
        float b00 = sBa[cl], b01 = sBa[cl + 1];
        float b10 = sBa[cl + 8], b11 = sBa[cl + 9];
        ah[kk][0] = h2pk(sspf(c[2 * kk][0] + b00), sspf(c[2 * kk][1] + b01));
        ah[kk][1] = h2pk(sspf(c[2 * kk][2] + b00), sspf(c[2 * kk][3] + b01));
        ah[kk][2] = h2pk(sspf(c[2 * kk + 1][0] + b10), sspf(c[2 * kk + 1][1] + b11));
        ah[kk][3] = h2pk(sspf(c[2 * kk + 1][2] + b10), sspf(c[2 * kk + 1][3] + b11));
    }

    float d[8][4];
#pragma unroll
    for (int nb = 0; nb < 8; nb++)
#pragma unroll
        for (int q = 0; q < 4; q++) d[nb][q] = 0.f;

#pragma unroll
    for (int kk = 0; kk < 4; kk++) {
        const unsigned* brow = sWbH + (kk * 4 + t) * 136;
#pragma unroll
        for (int nb = 0; nb < 8; nb++) {
            uint2 bv = *(const uint2*)&brow[2 * (nb * 8 + g)];
            mma_f16(d[nb][0], d[nb][1], d[nb][2], d[nb][3],
                    ah[kk][0], ah[kk][1], ah[kk][2], ah[kk][3], bv.x, bv.y);
        }
    }

    int nA = n0 + R0 + g;
    int nB = n0 + R0 + g + 8;
#pragma unroll
    for (int nb = 0; nb < 8; nb++) {
        int col = nb * 8 + 2 * t;
        float b0 = sBb[col], b1 = sBb[col + 1];
        float2 rA = make_float2(0.f, 0.f), rB = make_float2(0.f, 0.f);
        if (nA < N_NODES) {
            float2 prev = *(const float2*)&g_out[(size_t)nA * D1 + col];
            rA.x = d[nb][0] + b0 + prev.x;
            rA.y = d[nb][1] + b1 + prev.y;
            *(float2*)&g_out[(size_t)nA * D1 + col] = rA;
        }
        if (nB < N_NODES) {
            float2 prev = *(const float2*)&g_out[(size_t)nB * D1 + col];
            rB.x = d[nb][2] + b0 + prev.x;
            rB.y = d[nb][3] + b1 + prev.y;
            *(float2*)&g_out[(size_t)nB * D1 + col] = rB;
        }
        *(float2*)&sBuf[(R0 + g) * 72 + col] = rA;
        *(float2*)&sBuf[(R0 + g + 8) * 72 + col] = rB;
    }
    __syncthreads();

    {
        int col = tid & 63, q = tid >> 6;
        float ps = 0.f, pq = 0.f;
        for (int r = 32 * q; r < 32 * q + 32; r++) {
            float v = sBuf[r * 72 + col];
            ps += v;
            pq += v * v;
        }
        atomicAdd(&sSum[col], ps);
        atomicAdd(&sSq[col], pq);
    }
    __syncthreads();
    if (tid < 64) {
        atomicAdd(&g_bnstats[tid], sSum[tid]);
        atomicAdd(&g_bnstats[64 + tid], sSq[tid]);
    }
}

// =====================================================================
// pool with fused layer-2 BN
// =====================================================================
__global__ __launch_bounds__(256) void k_pool(const int* __restrict__ batch,
                                              const float* __restrict__ bng,
                                              const float* __restrict__ bnb) {
    __shared__ float sSc[64], sOf[64];
    int tid = threadIdx.x;
    if (tid < 64) {
        const float invN = 1.f / (float)N_NODES;
        float mu = g_bnstats[tid] * invN;
        float var = fmaxf(g_bnstats[64 + tid] * invN - mu * mu, 0.f);
        float sc = rsqrtf(var + BN_EPS) * bng[tid];
        sSc[tid] = sc;
        sOf[tid] = bnb[tid] - mu * sc;
    }
    __syncthreads();
    int idx = blockIdx.x * blockDim.x + tid;
    if (idx >= N_NODES * D1) return;
    int n = idx >> 6, f = idx & 63;
    int bg = batch[n];
    float v = g_out[idx] * sSc[f] + sOf[f];
    atomicAdd(&g_pool[bg * D1 + f], v);
    if (f == 0) atomicAdd(&g_cnt[bg], 1.f);
}

__global__ void k_head(const float* __restrict__ postW, const float* __restrict__ postb,
                       const float* __restrict__ outW, const float* __restrict__ outb,
                       float* __restrict__ y) {
    int g = blockIdx.x;
    int f = threadIdx.x;
    __shared__ float sp[64];
    __shared__ float sr[2];
    float cnt = fmaxf(g_cnt[g], 1.f);
    sp[f] = g_pool[g * D1 + f] / cnt;
    __syncthreads();
    float a = postb[f];
#pragma unroll
    for (int k = 0; k < 64; k++) a = fmaf(sp[k], postW[f * 64 + k], a);
    float hp = fmaxf(a, 0.f) * outW[f];
#pragma unroll
    for (int o = 16; o > 0; o >>= 1) hp += __shfl_down_sync(0xffffffffu, hp, o);
    if ((f & 31) == 0) sr[f >> 5] = hp;
    __syncthreads();
    if (f == 0) y[g] = sr[0] + sr[1] + outb[0];
}

// =====================================================================
extern "C" void kernel_launch(void* const* d_in, const int* in_sizes, int n_in,
                              void* d_out, int out_size) {
    const float* x      = (const float*)d_in[0];
    const float* ew     = (const float*)d_in[1];
    const float* ea     = (const float*)d_in[2];
    const int*   ei     = (const int*)d_in[3];
    const int*   batch  = (const int*)d_in[4];
    const float* pre_W  = (const float*)d_in[5];
    const float* pre_b  = (const float*)d_in[6];
    const float* mlp_W1 = (const float*)d_in[7];
    const float* mlp_b1 = (const float*)d_in[8];
    const float* mlp_W2 = (const float*)d_in[9];
    const float* mlp_b2 = (const float*)d_in[10];
    const float* cf_W1  = (const float*)d_in[11];
    const float* cf_W2  = (const float*)d_in[12];
    const float* cf_b2  = (const float*)d_in[13];
    const float* int_W  = (const float*)d_in[14];
    const float* int_b  = (const float*)d_in[15];
    const float* bn_g   = (const float*)d_in[16];
    const float* bn_b   = (const float*)d_in[17];
    const float* post_W = (const float*)d_in[18];
    const float* post_b = (const float*)d_in[19];
    const float* out_W  = (const float*)d_in[20];
    const float* out_b  = (const float*)d_in[21];
    float* y = (float*)d_out;

    void *agg_p, *bn_p, *pool_p, *cnt_p, *hist_p;
    cudaGetSymbolAddress(&agg_p, g_agg);
    cudaGetSymbolAddress(&bn_p, g_bnstats);
    cudaGetSymbolAddress(&pool_p, g_pool);
    cudaGetSymbolAddress(&cnt_p, g_cnt);
    cudaGetSymbolAddress(&hist_p, g_hist);

    cudaFuncSetAttribute(k_edge, cudaFuncAttributeMaxDynamicSharedMemorySize, EDGE_SMEM);
    cudaFuncSetAttribute(k_node, cudaFuncAttributeMaxDynamicSharedMemorySize, NODE_SMEM);
    cudaFuncSetAttribute(k_lin1, cudaFuncAttributeMaxDynamicSharedMemorySize, LIN1_SMEM);
    cudaFuncSetAttribute(k_pre, cudaFuncAttributeMaxDynamicSharedMemorySize, PRE_SMEM);

    // counting sort of edges by dst (scatter writes packed sorted meta)
    cudaMemsetAsync(hist_p, 0, N_NODES * sizeof(int));
    k_hist<<<(N_EDGES + 255) / 256, 256>>>(ei);
    k_scan<<<1, 1024>>>();
    k_scatter<<<(N_EDGES + 255) / 256, 256>>>(ei, ew);

    k_pre<<<(N_NODES + 127) / 128, 256, PRE_SMEM>>>(x, pre_W, pre_b);
    cudaMemsetAsync(pool_p, 0, N_GRAPHS * D1 * sizeof(float));
    cudaMemsetAsync(cnt_p, 0, N_GRAPHS * sizeof(float));

    for (int l = 0; l < 3; l++) {
        k_lin1<<<(N_NODES + 127) / 128, 256, LIN1_SMEM>>>(
            cf_W1 + l * 64 * 64,
            bn_g + (l > 0 ? (l - 1) * 64 : 0),
            bn_b + (l > 0 ? (l - 1) * 64 : 0),
            l > 0 ? 1 : 0);
        cudaMemsetAsync(agg_p, 0, (size_t)N_NODES * D1 * sizeof(float));
        cudaMemsetAsync(bn_p, 0, 2 * D1 * sizeof(float));
        k_edge<<<EDGE_GRID, 256, EDGE_SMEM>>>(ea,
                                              mlp_W1 + l * 64 * 50, mlp_b1 + l * 64,
                                              mlp_W2 + l * 64 * 64, mlp_b2 + l * 64);
        k_node<<<(N_NODES + 127) / 128, 256, NODE_SMEM>>>(cf_W2 + l * 64 * 64, cf_b2 + l * 64,
                                                          int_W + l * 64 * 64, int_b + l * 64);
    }

    k_pool<<<(N_NODES * D1 + 255) / 256, 256>>>(batch, bn_g + 2 * 64, bn_b + 2 * 64);
    k_head<<<N_GRAPHS, 64>>>(post_W, post_b, out_W, out_b, y);
}